// round 16
// baseline (speedup 1.0000x reference)
#include <cuda_runtime.h>
#include <cuda_fp16.h>
#include <cstdint>

#define N_ATOMS 100000
#define EDGES   400000
#define BGR     1024
#define FXD     78
#define DIM     32
#define OUTD    128
#define EMBD    128
#define VOCAB   26
#define NFLT    32
#define SEQ     1000
#define KW      8
#define CONVL   993           // SEQ - KW + 1
#define FLAT    31776         // NFLT * CONVL
#define COMB    2304          // 2*OUTD + 2*1024
#define H1DIM   1024
#define H2DIM   256
#define LMDIM   1024
#define NB_SCAN ((N_ATOMS + 255) / 256)   // 391
#define NPROJ   ((N_ATOMS + 7) / 8)       // 12500 proj blocks (8 nodes each)
#define NZERO   512                       // zero+hist blocks

#define SPLITS_XT 37
#define CPS_XT    27             // 37*27 = 999 >= 993 chunks (1 chunk = 1 tpos)
#define TOKSLAB   (CPS_XT + KW)  // 35 tokens per protein per split
#define LUTH      40             // padded filter-dim stride (halfs, 80B)

// ------------------------- scratch (device globals) -------------------------
__device__ float g_p[N_ATOMS * DIM];
__device__ float g_y[N_ATOMS * DIM];
__device__ float g_y2[N_ATOMS * DIM];
__device__ float g_stats[5 * 2 * DIM];
__device__ float g_xg[BGR * DIM];
__device__ __half g_luth[KW * VOCAB * LUTH];   // [k][v][f padded], fp16

// CSR scratch (g_deg / g_scanpkt are zeroed by scatter_kernel at the END of
// each replay; static zero-init covers the very first call)
__device__ int g_deg[N_ATOMS];
__device__ int g_rowptr[N_ATOMS + 1];
__device__ int g_cur[N_ATOMS];
__device__ int g_esorted[EDGES];
__device__ unsigned long long g_scanpkt[512];  // (flag<<32)|value, lookback scan

// fp16 weight & activation buffers
__device__ __half g_BxtH[(size_t)OUTD * FLAT];   // fc1_xt_w reorder+T, single fp16
__device__ __half g_B1H[(size_t)H1DIM * COMB];   // fc1_w^T hi
__device__ __half g_B1L[(size_t)H1DIM * COMB];   // fc1_w^T lo
__device__ __half g_B2H[(size_t)H2DIM * H1DIM];  // fc2_w^T hi
__device__ __half g_B2L[(size_t)H2DIM * H1DIM];  // fc2_w^T lo
__device__ __half g_XCh[(size_t)BGR * COMB];     // xc single fp16

__device__ float g_xtacc[BGR * OUTD];
__device__ float g_h1acc[BGR * H1DIM];
__device__ float g_h2acc[BGR * H2DIM];

__device__ __forceinline__ void split16(float v, __half& h, __half& l) {
    h = __float2half_rn(v);
    l = __float2half_rn(v - __half2float(h));
}

// ====== combo: proj78 (blocks < NPROJ) + zero/hist (remaining blocks) =======
__global__ void __launch_bounds__(256) combo_kernel(
    const float* __restrict__ x, const float* __restrict__ wa,
    float* __restrict__ p, const int* __restrict__ dst)
{
    __shared__ float wa_s[FXD * DIM];
    int tid = threadIdx.x;

    if (blockIdx.x < NPROJ) {
        // ---- proj78: p = x @ W1a ----
        for (int i = tid; i < FXD * DIM; i += blockDim.x) wa_s[i] = wa[i];
        __syncthreads();
        int lane = tid & 31;
        int node = blockIdx.x * 8 + (tid >> 5);
        if (node >= N_ATOMS) return;
        const float* row = x + (size_t)node * FXD;
        float acc = 0.f;
#pragma unroll 4
        for (int c = 0; c < FXD; c++)
            acc = fmaf(__ldg(row + c), wa_s[c * DIM + lane], acc);
        p[node * DIM + lane] = acc;
    } else {
        // ---- zero accumulators + edge histogram ----
        int idx = (blockIdx.x - NPROJ) * 256 + tid;
        int stride = NZERO * 256;
        for (int i = idx; i < BGR * OUTD; i += stride) g_xtacc[i] = 0.f;
        for (int i = idx; i < BGR * H1DIM; i += stride) g_h1acc[i] = 0.f;
        for (int i = idx; i < BGR * H2DIM; i += stride) g_h2acc[i] = 0.f;
        for (int i = idx; i < BGR * DIM; i += stride) g_xg[i] = 0.f;
        for (int i = idx; i < 5 * 2 * DIM; i += stride) g_stats[i] = 0.f;
        for (int e = idx; e < EDGES; e += stride) atomicAdd(&g_deg[dst[e]], 1);
    }
}

// single-pass decoupled-lookback exclusive scan of g_deg -> g_rowptr/g_cur
__global__ void scanlb_kernel() {
    __shared__ int s[256];
    __shared__ int exc;
    int tid = threadIdx.x;
    int b = blockIdx.x;
    int i = b * 256 + tid;
    int v = (i < N_ATOMS) ? g_deg[i] : 0;
    s[tid] = v;
    __syncthreads();
#pragma unroll
    for (int o = 1; o < 256; o <<= 1) {
        int u = (tid >= o) ? s[tid - o] : 0;
        __syncthreads();
        s[tid] += u;
        __syncthreads();
    }
    if (tid == 0) {
        int agg = s[255];
        if (b == 0) {
            atomicExch(&g_scanpkt[0], (2ULL << 32) | (unsigned)agg);
            exc = 0;
            g_rowptr[N_ATOMS] = EDGES;
        } else {
            atomicExch(&g_scanpkt[b], (1ULL << 32) | (unsigned)agg);
            int run = 0;
            for (int pb = b - 1; ; pb--) {
                unsigned long long pkt;
                do { pkt = atomicAdd(&g_scanpkt[pb], 0ULL); } while ((pkt >> 32) == 0);
                run += (int)(unsigned)pkt;
                if ((pkt >> 32) == 2ULL) break;
            }
            atomicExch(&g_scanpkt[b], (2ULL << 32) | (unsigned)(run + agg));
            exc = run;
        }
    }
    __syncthreads();
    if (i < N_ATOMS) {
        int val = s[tid] - v + exc;
        g_rowptr[i] = val;
        g_cur[i] = val;
    }
}

// scatter + reset deg/scanpkt for the NEXT replay
__global__ void scatter_kernel(const int* __restrict__ src, const int* __restrict__ dst) {
    int e = blockIdx.x * blockDim.x + threadIdx.x;
    if (e < N_ATOMS) g_deg[e] = 0;
    if (e < 512) g_scanpkt[e] = 0ULL;
    if (e >= EDGES) return;
    int pos = atomicAdd(&g_cur[dst[e]], 1);
    g_esorted[pos] = src[e];
}

// ------ merged weight transpose + fp16 split for fc1 (z=0) and fc2 (z=1) ----
__global__ void w16t2_kernel(const float* __restrict__ W1,
                             __half* __restrict__ B1h, __half* __restrict__ B1l,
                             const float* __restrict__ W2,
                             __half* __restrict__ B2h, __half* __restrict__ B2l)
{
    const float* W; __half *Bh, *Bl; int K, N;
    if (blockIdx.z == 0) { W = W1; Bh = B1h; Bl = B1l; K = COMB; N = H1DIM; }
    else {
        if (blockIdx.x >= H1DIM / 32 || blockIdx.y >= H2DIM / 32) return;
        W = W2; Bh = B2h; Bl = B2l; K = H1DIM; N = H2DIM;
    }
    __shared__ float ts[32][33];
    int k0 = blockIdx.x * 32, n0 = blockIdx.y * 32;
    int tx = threadIdx.x & 31, ty = threadIdx.x >> 5;
#pragma unroll
    for (int i = 0; i < 4; i++)
        ts[ty + i * 8][tx] = W[(size_t)(k0 + ty + i * 8) * N + n0 + tx];
    __syncthreads();
#pragma unroll
    for (int i = 0; i < 4; i++) {
        int n = ty + i * 8;
        float v = ts[tx][n];
        __half h, l; split16(v, h, l);
        size_t o = (size_t)(n0 + n) * K + k0 + tx;
        Bh[o] = h; Bl[o] = l;
    }
}

// -- fc1_xt weight reorder+transpose (single fp16); extra x-block: conv LUT --
__global__ void w16tx_kernel(const float* __restrict__ W,
                             const float* __restrict__ emb,
                             const float* __restrict__ cw,
                             __half* __restrict__ Bh)
{
    if (blockIdx.x == CONVL) {     // LUT blocks: [k][v][f] padded fp16 layout
        const int QTR = KW * NFLT * VOCAB / 4;   // 1664
        int base = blockIdx.y * QTR;
        for (int i = threadIdx.x; i < QTR; i += 256) {
            int idx = base + i;
            int f = idx % NFLT;
            int v = (idx / NFLT) % VOCAB;
            int k = idx / (NFLT * VOCAB);
            float acc = 0.f;
#pragma unroll 4
            for (int c = 0; c < EMBD; c++)
                acc = fmaf(emb[v * EMBD + c], cw[f * EMBD * KW + c * KW + k], acc);
            g_luth[(k * VOCAB + v) * LUTH + f] = __float2half_rn(acc);
        }
        return;
    }
    __shared__ float ts[32][33];
    int t = blockIdx.x;
    int n0 = blockIdx.y * 32;
    int tx = threadIdx.x & 31, ty = threadIdx.x >> 5;
#pragma unroll
    for (int i = 0; i < 4; i++) {
        int f = ty + i * 8;
        ts[f][tx] = W[(size_t)(f * CONVL + t) * OUTD + n0 + tx];
    }
    __syncthreads();
#pragma unroll
    for (int i = 0; i < 4; i++) {
        int n = ty + i * 8;
        Bh[(size_t)(n0 + n) * FLAT + t * 32 + tx] = __float2half_rn(ts[tx][n]);
    }
}

// =========================== fp16 MMA helpers ================================
#define ASTR 40
#define STG_H (128 * ASTR)       // stage stride in halfs (5120)
#define STG_B (STG_H * 2)        // stage stride in bytes (10240)

__device__ __forceinline__ uint32_t smem_u32(const void* p) {
    uint32_t a;
    asm("{ .reg .u64 t; cvta.to.shared.u64 t, %1; cvt.u32.u64 %0, t; }"
        : "=r"(a) : "l"(p));
    return a;
}
__device__ __forceinline__ void ldm4(uint32_t* r, uint32_t saddr) {
    asm volatile("ldmatrix.sync.aligned.m8n8.x4.shared.b16 {%0,%1,%2,%3}, [%4];"
        : "=r"(r[0]), "=r"(r[1]), "=r"(r[2]), "=r"(r[3]) : "r"(saddr));
}
__device__ __forceinline__ void mma16816(float* d, const uint32_t* a,
                                         uint32_t b0, uint32_t b1) {
    asm volatile(
        "mma.sync.aligned.m16n8k16.row.col.f32.f16.f16.f32 "
        "{%0,%1,%2,%3}, {%4,%5,%6,%7}, {%8,%9}, {%0,%1,%2,%3};"
        : "+f"(d[0]), "+f"(d[1]), "+f"(d[2]), "+f"(d[3])
        : "r"(a[0]), "r"(a[1]), "r"(a[2]), "r"(a[3]), "r"(b0), "r"(b1));
}

// ==== hgemm1: fc1 — A single fp16, B hi/lo, double-buffered, split-K ========
#define HG_A   0
#define HG_BH  (2 * STG_B)
#define HG_BL  (4 * STG_B)
#define HG_TOTAL (6 * STG_B)

__global__ void __launch_bounds__(256, 2) hgemm1(
    const __half* __restrict__ Ah,
    const __half* __restrict__ Bh, const __half* __restrict__ Bl,
    float* __restrict__ Cacc, int lda, int ldb, int ldc,
    int totalChunks, int chunksPerSplit)
{
    extern __shared__ char dsm[];
    __half* sAh = (__half*)(dsm + HG_A);
    __half* sBh = (__half*)(dsm + HG_BH);
    __half* sBl = (__half*)(dsm + HG_BL);

    int tid = threadIdx.x, lane = tid & 31, wid = tid >> 5;
    int mw = wid & 3, nw = wid >> 2;
    int m0 = blockIdx.y * 128, n0 = blockIdx.x * 128;

    int c0 = blockIdx.z * chunksPerSplit;
    int c1 = min(totalChunks, c0 + chunksPerSplit);
    if (c0 >= c1) return;

    int r = tid >> 1, q = (tid & 1) * 16;
    const __half* pAh = Ah + (size_t)(m0 + r) * lda + q;
    const __half* pBh = Bh + (size_t)(n0 + r) * ldb + q;
    const __half* pBl = Bl + (size_t)(n0 + r) * ldb + q;
    __half* sAh_w = sAh + r * ASTR + q;
    __half* sBh_w = sBh + r * ASTR + q;
    __half* sBl_w = sBl + r * ASTR + q;

    uint32_t bAh = smem_u32(sAh);
    uint32_t bBh = smem_u32(sBh), bBl = smem_u32(sBl);
    int lrow = lane & 15, lcol = (lane >> 4) * 8;
    uint32_t ofsA[2], ofsB[4];
#pragma unroll
    for (int mt = 0; mt < 2; mt++)
        ofsA[mt] = ((mw * 32 + mt * 16 + lrow) * ASTR + lcol) * 2;
#pragma unroll
    for (int ng = 0; ng < 4; ng++)
        ofsB[ng] = ((nw * 64 + ng * 16 + lrow) * ASTR + lcol) * 2;

    float acc[2][8][4] = {};
    int p = 0;

    for (int c = c0; c < c1; c++) {
        size_t k0 = (size_t)c * 32;
        int sofh = p * STG_H;
        uint32_t sofb = p * STG_B;
        float4 v0, v1;
        v0 = *(const float4*)(pAh + k0); v1 = *(const float4*)(pAh + k0 + 8);
        *(float4*)(sAh_w + sofh) = v0; *(float4*)(sAh_w + sofh + 8) = v1;
        v0 = *(const float4*)(pBh + k0); v1 = *(const float4*)(pBh + k0 + 8);
        *(float4*)(sBh_w + sofh) = v0; *(float4*)(sBh_w + sofh + 8) = v1;
        v0 = *(const float4*)(pBl + k0); v1 = *(const float4*)(pBl + k0 + 8);
        *(float4*)(sBl_w + sofh) = v0; *(float4*)(sBl_w + sofh + 8) = v1;
        __syncthreads();

#pragma unroll
        for (int ks = 0; ks < 2; ks++) {
            uint32_t ah[2][4];
            ldm4(ah[0], bAh + sofb + ofsA[0] + ks * 32);
            ldm4(ah[1], bAh + sofb + ofsA[1] + ks * 32);
#pragma unroll
            for (int ng = 0; ng < 4; ng++) {
                uint32_t bh[4], bl[4];
                ldm4(bh, bBh + sofb + ofsB[ng] + ks * 32);
                ldm4(bl, bBl + sofb + ofsB[ng] + ks * 32);
#pragma unroll
                for (int mt = 0; mt < 2; mt++) {
                    float* d0 = acc[mt][2 * ng];
                    float* d1 = acc[mt][2 * ng + 1];
                    mma16816(d0, ah[mt], bh[0], bh[2]);
                    mma16816(d0, ah[mt], bl[0], bl[2]);
                    mma16816(d1, ah[mt], bh[1], bh[3]);
                    mma16816(d1, ah[mt], bl[1], bl[3]);
                }
            }
        }
        p ^= 1;
    }

    int gid = lane >> 2, tig = lane & 3;
#pragma unroll
    for (int mt = 0; mt < 2; mt++) {
        int row = m0 + mw * 32 + mt * 16 + gid;
#pragma unroll
        for (int nt = 0; nt < 8; nt++) {
            int col = n0 + nw * 64 + nt * 8 + tig * 2;
            float* p0 = Cacc + (size_t)row * ldc + col;
            float* p1 = Cacc + (size_t)(row + 8) * ldc + col;
            atomicAdd(p0,     acc[mt][nt][0]);
            atomicAdd(p0 + 1, acc[mt][nt][1]);
            atomicAdd(p1,     acc[mt][nt][2]);
            atomicAdd(p1 + 1, acc[mt][nt][3]);
        }
    }
}

// == f2gemm: fc2 — A from fp32 h1acc (+bias,relu) split hi/lo in-kernel ======
__global__ void __launch_bounds__(256, 2) f2gemm(
    const float* __restrict__ Aacc, const float* __restrict__ abias,
    const __half* __restrict__ Bh, const __half* __restrict__ Bl,
    float* __restrict__ Cacc, int lda, int ldb, int ldc,
    int totalChunks, int chunksPerSplit)
{
    __shared__ __half sAh[128 * ASTR], sAl[128 * ASTR];
    __shared__ __half sBh[128 * ASTR], sBl[128 * ASTR];

    int tid = threadIdx.x, lane = tid & 31, wid = tid >> 5;
    int mw = wid & 3, nw = wid >> 2;
    int m0 = blockIdx.y * 128, n0 = blockIdx.x * 128;

    int c0 = blockIdx.z * chunksPerSplit;
    int c1 = min(totalChunks, c0 + chunksPerSplit);
    if (c0 >= c1) return;

    int r = tid >> 1, q = (tid & 1) * 16;
    const float* pA = Aacc + (size_t)(m0 + r) * lda + q;
    const __half* pBh = Bh + (size_t)(n0 + r) * ldb + q;
    const __half* pBl = Bl + (size_t)(n0 + r) * ldb + q;
    __half* sAh_w = sAh + r * ASTR + q;
    __half* sAl_w = sAl + r * ASTR + q;
    __half* sBh_w = sBh + r * ASTR + q;
    __half* sBl_w = sBl + r * ASTR + q;

    uint32_t bAh = smem_u32(sAh), bAl = smem_u32(sAl);
    uint32_t bBh = smem_u32(sBh), bBl = smem_u32(sBl);
    int lrow = lane & 15, lcol = (lane >> 4) * 8;
    uint32_t ofsA[2], ofsB[4];
#pragma unroll
    for (int mt = 0; mt < 2; mt++)
        ofsA[mt] = ((mw * 32 + mt * 16 + lrow) * ASTR + lcol) * 2;
#pragma unroll
    for (int ng = 0; ng < 4; ng++)
        ofsB[ng] = ((nw * 64 + ng * 16 + lrow) * ASTR + lcol) * 2;

    float acc[2][8][4] = {};

    for (int c = c0; c < c1; c++) {
        size_t k0 = (size_t)c * 32;
        float av[16];
#pragma unroll
        for (int i = 0; i < 4; i++)
            *(float4*)&av[i * 4] = *(const float4*)(pA + k0 + i * 4);
        __half2 hh[8], ll[8];
#pragma unroll
        for (int i = 0; i < 8; i++) {
            float u0 = fmaxf(av[i * 2]     + __ldg(abias + k0 + q + i * 2),     0.f);
            float u1 = fmaxf(av[i * 2 + 1] + __ldg(abias + k0 + q + i * 2 + 1), 0.f);
            __half h0, l0, h1, l1;
            split16(u0, h0, l0); split16(u1, h1, l1);
            hh[i] = __halves2half2(h0, h1);
            ll[i] = __halves2half2(l0, l1);
        }
        *(float4*)sAh_w = *(float4*)&hh[0];
        *(float4*)(sAh_w + 8) = *(float4*)&hh[4];
        *(float4*)sAl_w = *(float4*)&ll[0];
        *(float4*)(sAl_w + 8) = *(float4*)&ll[4];

        float4 v0, v1;
        v0 = *(const float4*)(pBh + k0); v1 = *(const float4*)(pBh + k0 + 8);
        *(float4*)sBh_w = v0; *(float4*)(sBh_w + 8) = v1;
        v0 = *(const float4*)(pBl + k0); v1 = *(const float4*)(pBl + k0 + 8);
        *(float4*)sBl_w = v0; *(float4*)(sBl_w + 8) = v1;
        __syncthreads();

#pragma unroll
        for (int ks = 0; ks < 2; ks++) {
            uint32_t ah[2][4], al[2][4];
            ldm4(ah[0], bAh + ofsA[0] + ks * 32);
            ldm4(ah[1], bAh + ofsA[1] + ks * 32);
            ldm4(al[0], bAl + ofsA[0] + ks * 32);
            ldm4(al[1], bAl + ofsA[1] + ks * 32);
#pragma unroll
            for (int ng = 0; ng < 4; ng++) {
                uint32_t bh[4], bl[4];
                ldm4(bh, bBh + ofsB[ng] + ks * 32);
                ldm4(bl, bBl + ofsB[ng] + ks * 32);
#pragma unroll
                for (int mt = 0; mt < 2; mt++) {
                    float* d0 = acc[mt][2 * ng];
                    float* d1 = acc[mt][2 * ng + 1];
                    mma16816(d0, ah[mt], bh[0], bh[2]);
                    mma16816(d0, ah[mt], bl[0], bl[2]);
                    mma16816(d0, al[mt], bh[0], bh[2]);
                    mma16816(d1, ah[mt], bh[1], bh[3]);
                    mma16816(d1, ah[mt], bl[1], bl[3]);
                    mma16816(d1, al[mt], bh[1], bh[3]);
                }
            }
        }
        __syncthreads();
    }

    int gid = lane >> 2, tig = lane & 3;
#pragma unroll
    for (int mt = 0; mt < 2; mt++) {
        int row = m0 + mw * 32 + mt * 16 + gid;
#pragma unroll
        for (int nt = 0; nt < 8; nt++) {
            int col = n0 + nw * 64 + nt * 8 + tig * 2;
            float* p0 = Cacc + (size_t)row * ldc + col;
            float* p1 = Cacc + (size_t)(row + 8) * ldc + col;
            atomicAdd(p0,     acc[mt][nt][0]);
            atomicAdd(p0 + 1, acc[mt][nt][1]);
            atomicAdd(p1,     acc[mt][nt][2]);
            atomicAdd(p1 + 1, acc[mt][nt][3]);
        }
    }
}

// == fused conv + fc1_xt GEMM: fp16 LUT/A, single-fp16 B, double-buffered ====
#define CG_LUT   0
#define CG_BIAS  (CG_LUT + KW * VOCAB * LUTH * 2)          // 16640
#define CG_TOK   (CG_BIAS + 128)                            // 16768
#define CG_AH    (CG_TOK + 128 * TOKSLAB * 4)               // 34688
#define CG_BH    (CG_AH + 2 * STG_B)                        // 55168
#define CG_TOTAL (CG_BH + 2 * STG_B)                        // 75648

__global__ void __launch_bounds__(256, 2) cgemm(
    const int* __restrict__ target, const float* __restrict__ convbias,
    const __half* __restrict__ Bh, float* __restrict__ Cacc)
{
    extern __shared__ char dsm[];
    __half* lut_s = (__half*)(dsm + CG_LUT);
    float* bias_s = (float*)(dsm + CG_BIAS);
    int*   tok_s  = (int*)(dsm + CG_TOK);
    __half* sAh = (__half*)(dsm + CG_AH);
    __half* sBh = (__half*)(dsm + CG_BH);

    int tid = threadIdx.x, lane = tid & 31, wid = tid >> 5;
    int mw = wid & 3, nw = wid >> 2;
    int m0 = blockIdx.y * 128;

    int c0 = blockIdx.z * CPS_XT;
    int c1 = min(CONVL, c0 + CPS_XT);
    if (c0 >= c1) return;

    for (int i = tid; i < KW * VOCAB * LUTH / 2; i += 256)
        ((uint32_t*)lut_s)[i] = ((const uint32_t*)g_luth)[i];
    if (tid < NFLT) bias_s[tid] = convbias[tid];
    for (int i = tid; i < 128 * TOKSLAB; i += 256) {
        int row = i / TOKSLAB, j = i - row * TOKSLAB;
        int tp = c0 + j;
        tok_s[i] = (tp < SEQ) ? target[(size_t)(m0 + row) * SEQ + tp] : 0;
    }

    int r = tid >> 1, q = (tid & 1) * 16;
    const __half* pBh = Bh + (size_t)r * FLAT + q;
    __half* sAh_w = sAh + r * ASTR + q;
    __half* sBh_w = sBh + r * ASTR + q;

    uint32_t bAh = smem_u32(sAh);
    uint32_t bBh = smem_u32(sBh);
    int lrow = lane & 15, lcol = (lane >> 4) * 8;
    uint32_t ofsA[2], ofsB[4];
#pragma unroll
    for (int mt = 0; mt < 2; mt++)
        ofsA[mt] = ((mw * 32 + mt * 16 + lrow) * ASTR + lcol) * 2;
#pragma unroll
    for (int ng = 0; ng < 4; ng++)
        ofsB[ng] = ((nw * 64 + ng * 16 + lrow) * ASTR + lcol) * 2;

    float acc[2][8][4] = {};
    __syncthreads();

    __half2 bias2[8];
#pragma unroll
    for (int i = 0; i < 8; i++)
        bias2[i] = __floats2half2_rn(bias_s[q + i * 2], bias_s[q + i * 2 + 1]);
    int tkreg[KW];
#pragma unroll
    for (int k = 0; k < KW; k++) tkreg[k] = tok_s[r * TOKSLAB + k];

    const __half2 z2 = __float2half2_rn(0.f);
    int p = 0;

    for (int c = c0; c < c1; c++) {
        int cc = c - c0;
        size_t k0 = (size_t)c * 32;
        float4 bh0 = *(const float4*)(pBh + k0);
        float4 bh1 = *(const float4*)(pBh + k0 + 8);

        __half2 a2[8];
#pragma unroll
        for (int i = 0; i < 8; i++) a2[i] = bias2[i];
#pragma unroll
        for (int k = 0; k < KW; k++) {
            const __half2* lp = (const __half2*)&lut_s[(k * VOCAB + tkreg[k]) * LUTH + q];
#pragma unroll
            for (int i = 0; i < 8; i++) a2[i] = __hadd2(a2[i], lp[i]);
        }
#pragma unroll
        for (int i = 0; i < 8; i++) a2[i] = __hmax2(a2[i], z2);

        int sofh = p * STG_H;
        uint32_t sofb = p * STG_B;
        *(float4*)(sAh_w + sofh) = *(float4*)&a2[0];
        *(float4*)(sAh_w + sofh + 8) = *(float4*)&a2[4];
        *(float4*)(sBh_w + sofh) = bh0; *(float4*)(sBh_w + sofh + 8) = bh1;

#pragma unroll
        for (int k = 0; k < KW - 1; k++) tkreg[k] = tkreg[k + 1];
        tkreg[KW - 1] = tok_s[r * TOKSLAB + cc + KW];
        __syncthreads();

#pragma unroll
        for (int ks = 0; ks < 2; ks++) {
            uint32_t ah[2][4];
            ldm4(ah[0], bAh + sofb + ofsA[0] + ks * 32);
            ldm4(ah[1], bAh + sofb + ofsA[1] + ks * 32);
#pragma unroll
            for (int ng = 0; ng < 4; ng++) {
                uint32_t bh[4];
                ldm4(bh, bBh + sofb + ofsB[ng] + ks * 32);
#pragma unroll
                for (int mt = 0; mt < 2; mt++) {
                    mma16816(acc[mt][2 * ng],     ah[mt], bh[0], bh[2]);
                    mma16816(acc[mt][2 * ng + 1], ah[mt], bh[1], bh[3]);
                }
            }
        }
        p ^= 1;
    }

    int gid = lane >> 2, tig = lane & 3;
#pragma unroll
    for (int mt = 0; mt < 2; mt++) {
        int row = m0 + mw * 32 + mt * 16 + gid;
#pragma unroll
        for (int nt = 0; nt < 8; nt++) {
            int col = nw * 64 + nt * 8 + tig * 2;
            float* p0 = Cacc + (size_t)row * OUTD + col;
            float* p1 = Cacc + (size_t)(row + 8) * OUTD + col;
            atomicAdd(p0,     acc[mt][nt][0]);
            atomicAdd(p0 + 1, acc[mt][nt][1]);
            atomicAdd(p1,     acc[mt][nt][2]);
            atomicAdd(p1 + 1, acc[mt][nt][3]);
        }
    }
}

// ------- warp gather over CSR: software-pipelined loads (MLP=2) --------------
__device__ __forceinline__ float gather_row(const float* __restrict__ yv,
                                            int i, int lane)
{
    int rr = (lane < 2) ? g_rowptr[i + lane] : 0;
    int r0 = __shfl_sync(0xffffffffu, rr, 0);
    int r1 = __shfl_sync(0xffffffffu, rr, 1);

    float t = yv[(size_t)i * DIM + lane];
    for (int base = r0; base < r1; base += 32) {
        int myE = base + lane;
        int s = (myE < r1) ? g_esorted[myE] : 0;
        int cnt = min(r1 - base, 32);
        int s0 = __shfl_sync(0xffffffffu, s, 0);
        float a = yv[(size_t)s0 * DIM + lane];
        for (int j = 1; j < cnt; j++) {
            int sj = __shfl_sync(0xffffffffu, s, j);
            float b = yv[(size_t)sj * DIM + lane];
            t += a;
            a = b;
        }
        t += a;
    }
    return t;
}

// ---- smem-broadcast matmul: acc += vec(32, in tbuf slot) @ W[32][32] --------
__device__ __forceinline__ float bcast_matvec(const float* __restrict__ tslot,
                                              const float* __restrict__ Ws,
                                              int lane, float acc)
{
#pragma unroll
    for (int k = 0; k < 8; k++) {
        float4 v = *(const float4*)&tslot[k * 4];   // broadcast LDS.128
        acc = fmaf(v.x, Ws[(k * 4 + 0) * DIM + lane], acc);
        acc = fmaf(v.y, Ws[(k * 4 + 1) * DIM + lane], acc);
        acc = fmaf(v.z, Ws[(k * 4 + 2) * DIM + lane], acc);
        acc = fmaf(v.w, Ws[(k * 4 + 3) * DIM + lane], acc);
    }
    return acc;
}

// ---- layer 0 tail: gather p + y = relu(relu(t+ba)@Wb + bb) + BN stats ------
__global__ void __launch_bounds__(256) mlp2agg_kernel(
    const float* __restrict__ p, const float* __restrict__ wb,
    const float* __restrict__ ba, const float* __restrict__ bb,
    float* __restrict__ y, float* __restrict__ stats)
{
    __shared__ float wb_s[DIM * DIM];
    __shared__ float tbuf[256];
    int tid = threadIdx.x;
    for (int i = tid; i < DIM * DIM; i += blockDim.x) wb_s[i] = wb[i];
    __syncthreads();

    int lane = tid & 31;
    float* tslot = &tbuf[tid & ~31];
    int warpId = blockIdx.x * (blockDim.x >> 5) + (tid >> 5);
    int nWarps = gridDim.x * (blockDim.x >> 5);
    float bav = ba[lane], bbv = bb[lane];
    float s0 = 0.f, s1 = 0.f;

    for (int i = warpId; i < N_ATOMS; i += nWarps) {
        float t = gather_row(p, i, lane);
        float hidden = fmaxf(t + bav, 0.f);
        tbuf[tid] = hidden;
        __syncwarp();
        float acc = bcast_matvec(tslot, wb_s, lane, bbv);
        __syncwarp();
        float yv = fmaxf(acc, 0.f);
        y[(size_t)i * DIM + lane] = yv;
        s0 += yv;
        s1 += yv * yv;
    }
    atomicAdd(&stats[lane], s0);
    atomicAdd(&stats[DIM + lane], s1);
}

// ====== fused full GIN layer (layers 1-4): BN fold + gather + MLP + stats ===
__global__ void __launch_bounds__(256) ginfull_kernel(
    const float* __restrict__ y_in, const float* __restrict__ wa,
    const float* __restrict__ ba, const float* __restrict__ wb,
    const float* __restrict__ bb, const float* __restrict__ gamma,
    const float* __restrict__ beta, const float* __restrict__ statsIn,
    float* __restrict__ y_out, float* __restrict__ statsOut)
{
    __shared__ float wa_s[DIM * DIM], wb_s[DIM * DIM];
    __shared__ float sc_s[DIM], sh_s[DIM], shwa_s[DIM];
    __shared__ float tbuf[256];
    int tid = threadIdx.x;
    if (tid < DIM) {
        float mu = statsIn[tid] * (1.0f / N_ATOMS);
        float var = statsIn[DIM + tid] * (1.0f / N_ATOMS) - mu * mu;
        float sc = gamma[tid] * rsqrtf(var + 1e-5f);
        sc_s[tid] = sc;
        sh_s[tid] = beta[tid] - mu * sc;
    }
    __syncthreads();
    for (int i = tid; i < DIM * DIM; i += blockDim.x) {
        wa_s[i] = sc_s[i >> 5] * wa[i];
        wb_s[i] = wb[i];
    }
    if (tid < DIM) {
        float acc = 0.f;
#pragma unroll
        for (int c = 0; c < DIM; c++) acc = fmaf(sh_s[c], wa[c * DIM + tid], acc);
        shwa_s[tid] = acc;
    }
    __syncthreads();

    int lane = tid & 31;
    float* tslot = &tbuf[tid & ~31];
    int warpId = blockIdx.x * (blockDim.x >> 5) + (tid >> 5);
    int nWarps = gridDim.x * (blockDim.x >> 5);
    float bav = ba[lane], bbv = bb[lane], shwav = shwa_s[lane];
    float s0 = 0.f, s1 = 0.f;

    for (int i = warpId; i < N_ATOMS; i += nWarps) {
        int rr = (lane < 2) ? g_rowptr[i + lane] : 0;
        int r0 = __shfl_sync(0xffffffffu, rr, 0);
        int r1 = __shfl_sync(0xffffffffu, rr, 1);
        int deg1 = r1 - r0 + 1;

        float t = gather_row(y_in, i, lane);

        tbuf[tid] = t;
        __syncwarp();
        float h1 = bcast_matvec(tslot, wa_s, lane,
                                fmaf((float)deg1, shwav, bav));
        __syncwarp();
        float hidden = fmaxf(h1, 0.f);
        tbuf[tid] = hidden;
        __syncwarp();
        float acc = bcast_matvec(tslot, wb_s, lane, bbv);
        __syncwarp();

        float yv = fmaxf(acc, 0.f);
        y_out[(size_t)i * DIM + lane] = yv;
        s0 += yv;
        s1 += yv * yv;
    }
    atomicAdd(&statsOut[lane], s0);
    atomicAdd(&statsOut[DIM + lane], s1);
}

// ---------- global add pool (segmented, batch sorted, BN inline) ------------
__global__ void pool2_kernel(const float* __restrict__ y, const int* __restrict__ batch,
                             const float* __restrict__ statsIn,
                             const float* __restrict__ gamma, const float* __restrict__ beta,
                             float* __restrict__ xg)
{
    int lane = threadIdx.x & 31;
    int warp = (blockIdx.x * blockDim.x + threadIdx.x) >> 5;
    int nb = warp * 32;
    if (nb >= N_ATOMS) return;
    float mu = statsIn[lane] * (1.0f / N_ATOMS);
    float var = statsIn[DIM + lane] * (1.0f / N_ATOMS) - mu * mu;
    float sc = gamma[lane] * rsqrtf(var + 1e-5f);
    float sh = beta[lane] - mu * sc;

    int bt = (nb + lane < N_ATOMS) ? batch[nb + lane] : -1;
    int cur = __shfl_sync(0xffffffffu, bt, 0);
    float sum = 0.f;
    int last = min(32, N_ATOMS - nb);
    for (int j = 0; j < last; j++) {
        int b = __shfl_sync(0xffffffffu, bt, j);
        float v = fmaf(y[(size_t)(nb + j) * DIM + lane], sc, sh);
        if (b != cur) {
            atomicAdd(&xg[cur * DIM + lane], sum);
            sum = 0.f; cur = b;
        }
        sum += v;
    }
    atomicAdd(&xg[cur * DIM + lane], sum);
}

// ----- build xc (single fp16): fc1_xd + xt epilogue + LM --------------------
__global__ void xcfill_kernel(const float* __restrict__ xg, const float* __restrict__ w,
                              const float* __restrict__ bias,
                              const float* __restrict__ xtacc, const float* __restrict__ xtb,
                              const float* __restrict__ drug, const float* __restrict__ prot)
{
    int idx = blockIdx.x * blockDim.x + threadIdx.x;
    if (idx >= BGR * COMB) return;
    int b = idx / COMB;
    int j = idx - b * COMB;
    float v;
    if (j < OUTD) {
        float acc = bias[j];
#pragma unroll
        for (int c = 0; c < DIM; c++) acc = fmaf(xg[b * DIM + c], w[c * OUTD + j], acc);
        v = fmaxf(acc, 0.f);
    } else if (j < 2 * OUTD) {
        int o = j - OUTD;
        v = fmaxf(xtacc[b * OUTD + o] + xtb[o], 0.f);
    } else {
        int jj = j - 2 * OUTD;
        v = (jj < LMDIM) ? drug[b * LMDIM + jj] : prot[b * LMDIM + (jj - LMDIM)];
    }
    g_XCh[idx] = __float2half_rn(v);
}

// ------------- final output layer (fc2 epilogue fused in) -------------------
__global__ void out_kernel(const float* __restrict__ h2acc, const float* __restrict__ b2,
                           const float* __restrict__ w, const float* __restrict__ b,
                           float* __restrict__ out)
{
    int tid = threadIdx.x;
    int lane = tid & 31;
    int row = blockIdx.x * (blockDim.x >> 5) + (tid >> 5);
    if (row >= BGR) return;
    float acc = 0.f;
#pragma unroll
    for (int k = 0; k < H2DIM / 32; k++) {
        float h2 = fmaxf(h2acc[row * H2DIM + k * 32 + lane] + b2[k * 32 + lane], 0.f);
        acc = fmaf(h2, w[k * 32 + lane], acc);
    }
#pragma unroll
    for (int off = 16; off; off >>= 1) acc += __shfl_xor_sync(0xffffffffu, acc, off);
    if (lane == 0) out[row] = acc + b[0];
}

// ================================ launcher ===================================
extern "C" void kernel_launch(void* const* d_in, const int* in_sizes, int n_in,
                              void* d_out, int out_size)
{
    (void)in_sizes; (void)n_in; (void)out_size;
    const float* x        = (const float*)d_in[0];
    const int*   ei       = (const int*)d_in[1];
    const int*   batch    = (const int*)d_in[2];
    const int*   target   = (const int*)d_in[3];
    const float* drug_lm  = (const float*)d_in[4];
    const float* prot_lm  = (const float*)d_in[5];
    const float* w1a      = (const float*)d_in[6];
    const float* b1a      = (const float*)d_in[7];
    const float* w1b      = (const float*)d_in[8];
    const float* b1b      = (const float*)d_in[9];
    const float* gw_a     = (const float*)d_in[10];
    const float* gb_a     = (const float*)d_in[11];
    const float* gw_b     = (const float*)d_in[12];
    const float* gb_b     = (const float*)d_in[13];
    const float* bn_gamma = (const float*)d_in[14];
    const float* bn_beta  = (const float*)d_in[15];
    const float* fc1_xd_w = (const float*)d_in[16];
    const float* fc1_xd_b = (const float*)d_in[17];
    const float* emb      = (const float*)d_in[18];
    const float* convxt_w = (const float*)d_in[19];
    const float* convxt_b = (const float*)d_in[20];
    const float* fc1_xt_w = (const float*)d_in[21];
    const float* fc1_xt_b = (const float*)d_in[22];
    const float* fc1_w    = (const float*)d_in[23];
    const float* fc1_b    = (const float*)d_in[24];
    const float* fc2_w    = (const float*)d_in[25];
    const float* fc2_b    = (const float*)d_in[26];
    const float* out_w    = (const float*)d_in[27];
    const float* out_b    = (const float*)d_in[28];
    float* out = (float*)d_out;

    const int* srcp = ei;
    const int* dstp = ei + EDGES;

    void* vp;
    cudaGetSymbolAddress(&vp, g_p);      float* p_p     = (float*)vp;
    cudaGetSymbolAddress(&vp, g_y);      float* p_y     = (float*)vp;
    cudaGetSymbolAddress(&vp, g_y2);     float* p_y2    = (float*)vp;
    cudaGetSymbolAddress(&vp, g_stats);  float* p_stats = (float*)vp;
    cudaGetSymbolAddress(&vp, g_xg);     float* p_xg    = (float*)vp;
    cudaGetSymbolAddress(&vp, g_BxtH);   __half* p_BxtH = (__half*)vp;
    cudaGetSymbolAddress(&vp, g_B1H);    __half* p_B1H  = (__half*)vp;
    cudaGetSymbolAddress(&vp, g_B1L);    __half* p_B1L  = (__half*)vp;
    cudaGetSymbolAddress(&vp, g_B2H);    __half* p_B2H  = (__half*)vp;
    cudaGetSymbolAddress(&vp, g_B2L);    __half* p_B2L  = (__half*)vp;
    cudaGetSymbolAddress(&vp, g_XCh);    __half* p_XCh  = (__half*)vp;
    cudaGetSymbolAddress(&vp, g_xtacc);  float* p_xtacc = (float*)vp;
    cudaGetSymbolAddress(&vp, g_h1acc);  float* p_h1acc = (float*)vp;
    cudaGetSymbolAddress(&vp, g_h2acc);  float* p_h2acc = (float*)vp;

    cudaFuncSetAttribute(cgemm, cudaFuncAttributeMaxDynamicSharedMemorySize, CG_TOTAL);
    cudaFuncSetAttribute(hgemm1, cudaFuncAttributeMaxDynamicSharedMemorySize, HG_TOTAL);

    // stream + fork/join events (capture-safe fork-join pattern)
    cudaStream_t s2;
    cudaStreamCreateWithFlags(&s2, cudaStreamNonBlocking);
    cudaEvent_t eFork, eJoin;
    cudaEventCreateWithFlags(&eFork, cudaEventDisableTiming);
    cudaEventCreateWithFlags(&eJoin, cudaEventDisableTiming);

    // (1) combo: proj78 + zero + hist   [main]
    combo_kernel<<<NPROJ + NZERO, 256>>>(x, w1a, p_p, dstp);
    cudaEventRecord(eFork, 0);

    // (2)(3)(4) CSR scan/scatter, then mlp2agg (submission #4 -> ncu capture)
    scanlb_kernel<<<NB_SCAN, 256>>>();
    scatter_kernel<<<(EDGES + 255) / 256, 256>>>(srcp, dstp);
    mlp2agg_kernel<<<1024, 256>>>(p_p, w1b, b1a, b1b, p_y, p_stats);

    // ---- branch B (s2): protein conv GEMM + weight conversions ----
    cudaStreamWaitEvent(s2, eFork, 0);
    { dim3 g(CONVL + 1, OUTD / 32);
      w16tx_kernel<<<g, 256, 0, s2>>>(fc1_xt_w, emb, convxt_w, p_BxtH); }
    {
        dim3 grid(1, BGR / 128, SPLITS_XT);
        cgemm<<<grid, 256, CG_TOTAL, s2>>>(target, convxt_b, p_BxtH, p_xtacc);
    }
    { dim3 g(COMB / 32, H1DIM / 32, 2);
      w16t2_kernel<<<g, 256, 0, s2>>>(fc1_w, p_B1H, p_B1L, fc2_w, p_B2H, p_B2L); }
    cudaEventRecord(eJoin, s2);

    // ---- branch A (main): GIN layers 1-4 + pool ----
    float* yin = p_y; float* yout = p_y2;
    for (int l = 1; l < 5; l++) {
        ginfull_kernel<<<1024, 256>>>(yin,
            gw_a + (l - 1) * DIM * DIM, gb_a + (l - 1) * DIM,
            gw_b + (l - 1) * DIM * DIM, gb_b + (l - 1) * DIM,
            bn_gamma + (l - 1) * DIM, bn_beta + (l - 1) * DIM,
            p_stats + (l - 1) * 2 * DIM, yout, p_stats + l * 2 * DIM);
        float* tmp = yin; yin = yout; yout = tmp;
    }
    pool2_kernel<<<(N_ATOMS / 32 + 7) / 8, 256>>>(yin, batch,
        p_stats + 4 * 2 * DIM, bn_gamma + 4 * DIM, bn_beta + 4 * DIM, p_xg);

    // join B: xcfill needs branch B's xtacc + weights
    cudaStreamWaitEvent(0, eJoin, 0);
    xcfill_kernel<<<(BGR * COMB + 255) / 256, 256>>>(
        p_xg, fc1_xd_w, fc1_xd_b, p_xtacc, fc1_xt_b, drug_lm, prot_lm);

    // head MLP
    {
        dim3 grid(H1DIM / 128, BGR / 128, 4);
        hgemm1<<<grid, 256, HG_TOTAL>>>(p_XCh, p_B1H, p_B1L, p_h1acc,
                                        COMB, COMB, H1DIM, COMB / 32, 18);
    }
    {
        dim3 grid(H2DIM / 128, BGR / 128, 16);
        f2gemm<<<grid, 256>>>(p_h1acc, fc1_b, p_B2H, p_B2L, p_h2acc,
                              H1DIM, H1DIM, H2DIM, H1DIM / 32, 2);
    }
    out_kernel<<<BGR / 8, 256>>>(p_h2acc, fc2_b, out_w, out_b, out);

    cudaEventDestroy(eFork);
    cudaEventDestroy(eJoin);
    cudaStreamDestroy(s2);
}

// round 17
// speedup vs baseline: 1.0559x; 1.0559x over previous
#include <cuda_runtime.h>
#include <cuda_fp16.h>
#include <cstdint>

#define N_ATOMS 100000
#define EDGES   400000
#define BGR     1024
#define FXD     78
#define DIM     32
#define OUTD    128
#define EMBD    128
#define VOCAB   26
#define NFLT    32
#define SEQ     1000
#define KW      8
#define CONVL   993           // SEQ - KW + 1
#define FLAT    31776         // NFLT * CONVL
#define COMB    2304          // 2*OUTD + 2*1024
#define H1DIM   1024
#define H2DIM   256
#define LMDIM   1024
#define NB_SCAN ((N_ATOMS + 255) / 256)   // 391
#define NPROJ   ((N_ATOMS + 7) / 8)       // 12500 proj blocks (8 nodes each)
#define NZERO   512                       // zero+hist blocks

#define SPLITS_XT 37
#define CPS_XT    27             // 37*27 = 999 >= 993 chunks (1 chunk = 1 tpos)
#define TOKSLAB   (CPS_XT + KW)  // 35 tokens per protein per split
#define LUTH      40             // padded filter-dim stride (halfs, 80B)

// ------------------------- scratch (device globals) -------------------------
__device__ float g_p[N_ATOMS * DIM];
__device__ float g_y[N_ATOMS * DIM];
__device__ float g_y2[N_ATOMS * DIM];
__device__ float g_stats[5 * 2 * DIM];
__device__ float g_xg[BGR * DIM];
__device__ __half g_luth[KW * VOCAB * LUTH];   // [k][v][f padded], fp16

// CSR scratch (g_deg / g_scanpkt are zeroed by scatter_kernel at the END of
// each replay; static zero-init covers the very first call)
__device__ int g_deg[N_ATOMS];
__device__ int g_rowptr[N_ATOMS + 1];
__device__ int g_cur[N_ATOMS];
__device__ int g_esorted[EDGES];
__device__ unsigned long long g_scanpkt[512];  // (flag<<32)|value, lookback scan

// fp16 weight & activation buffers
__device__ __half g_BxtH[(size_t)OUTD * FLAT];   // fc1_xt_w reorder+T, single fp16
__device__ __half g_B1H[(size_t)H1DIM * COMB];   // fc1_w^T hi
__device__ __half g_B1L[(size_t)H1DIM * COMB];   // fc1_w^T lo
__device__ __half g_B2H[(size_t)H2DIM * H1DIM];  // fc2_w^T hi
__device__ __half g_B2L[(size_t)H2DIM * H1DIM];  // fc2_w^T lo
__device__ __half g_XCh[(size_t)BGR * COMB];     // xc single fp16

__device__ float g_xtacc[BGR * OUTD];
__device__ float g_h1acc[BGR * H1DIM];
__device__ float g_h2acc[BGR * H2DIM];

__device__ __forceinline__ void split16(float v, __half& h, __half& l) {
    h = __float2half_rn(v);
    l = __float2half_rn(v - __half2float(h));
}

// ====== combo: proj78 (blocks < NPROJ) + zero/hist (remaining blocks) =======
__global__ void __launch_bounds__(256) combo_kernel(
    const float* __restrict__ x, const float* __restrict__ wa,
    float* __restrict__ p, const int* __restrict__ dst)
{
    __shared__ float wa_s[FXD * DIM];
    int tid = threadIdx.x;

    if (blockIdx.x < NPROJ) {
        for (int i = tid; i < FXD * DIM; i += blockDim.x) wa_s[i] = wa[i];
        __syncthreads();
        int lane = tid & 31;
        int node = blockIdx.x * 8 + (tid >> 5);
        if (node >= N_ATOMS) return;
        const float* row = x + (size_t)node * FXD;
        float acc = 0.f;
#pragma unroll 4
        for (int c = 0; c < FXD; c++)
            acc = fmaf(__ldg(row + c), wa_s[c * DIM + lane], acc);
        p[node * DIM + lane] = acc;
    } else {
        int idx = (blockIdx.x - NPROJ) * 256 + tid;
        int stride = NZERO * 256;
        for (int i = idx; i < BGR * OUTD; i += stride) g_xtacc[i] = 0.f;
        for (int i = idx; i < BGR * H1DIM; i += stride) g_h1acc[i] = 0.f;
        for (int i = idx; i < BGR * H2DIM; i += stride) g_h2acc[i] = 0.f;
        for (int i = idx; i < BGR * DIM; i += stride) g_xg[i] = 0.f;
        for (int i = idx; i < 5 * 2 * DIM; i += stride) g_stats[i] = 0.f;
        for (int e = idx; e < EDGES; e += stride) atomicAdd(&g_deg[dst[e]], 1);
    }
}

// single-pass decoupled-lookback exclusive scan of g_deg -> g_rowptr/g_cur
__global__ void scanlb_kernel() {
    __shared__ int s[256];
    __shared__ int exc;
    int tid = threadIdx.x;
    int b = blockIdx.x;
    int i = b * 256 + tid;
    int v = (i < N_ATOMS) ? g_deg[i] : 0;
    s[tid] = v;
    __syncthreads();
#pragma unroll
    for (int o = 1; o < 256; o <<= 1) {
        int u = (tid >= o) ? s[tid - o] : 0;
        __syncthreads();
        s[tid] += u;
        __syncthreads();
    }
    if (tid == 0) {
        int agg = s[255];
        if (b == 0) {
            atomicExch(&g_scanpkt[0], (2ULL << 32) | (unsigned)agg);
            exc = 0;
            g_rowptr[N_ATOMS] = EDGES;
        } else {
            atomicExch(&g_scanpkt[b], (1ULL << 32) | (unsigned)agg);
            int run = 0;
            for (int pb = b - 1; ; pb--) {
                unsigned long long pkt;
                do { pkt = atomicAdd(&g_scanpkt[pb], 0ULL); } while ((pkt >> 32) == 0);
                run += (int)(unsigned)pkt;
                if ((pkt >> 32) == 2ULL) break;
            }
            atomicExch(&g_scanpkt[b], (2ULL << 32) | (unsigned)(run + agg));
            exc = run;
        }
    }
    __syncthreads();
    if (i < N_ATOMS) {
        int val = s[tid] - v + exc;
        g_rowptr[i] = val;
        g_cur[i] = val;
    }
}

// scatter + reset deg/scanpkt for the NEXT replay
__global__ void scatter_kernel(const int* __restrict__ src, const int* __restrict__ dst) {
    int e = blockIdx.x * blockDim.x + threadIdx.x;
    if (e < N_ATOMS) g_deg[e] = 0;
    if (e < 512) g_scanpkt[e] = 0ULL;
    if (e >= EDGES) return;
    int pos = atomicAdd(&g_cur[dst[e]], 1);
    g_esorted[pos] = src[e];
}

// ------ merged weight transpose + fp16 split for fc1 (z=0) and fc2 (z=1) ----
__global__ void w16t2_kernel(const float* __restrict__ W1,
                             __half* __restrict__ B1h, __half* __restrict__ B1l,
                             const float* __restrict__ W2,
                             __half* __restrict__ B2h, __half* __restrict__ B2l)
{
    const float* W; __half *Bh, *Bl; int K, N;
    if (blockIdx.z == 0) { W = W1; Bh = B1h; Bl = B1l; K = COMB; N = H1DIM; }
    else {
        if (blockIdx.x >= H1DIM / 32 || blockIdx.y >= H2DIM / 32) return;
        W = W2; Bh = B2h; Bl = B2l; K = H1DIM; N = H2DIM;
    }
    __shared__ float ts[32][33];
    int k0 = blockIdx.x * 32, n0 = blockIdx.y * 32;
    int tx = threadIdx.x & 31, ty = threadIdx.x >> 5;
#pragma unroll
    for (int i = 0; i < 4; i++)
        ts[ty + i * 8][tx] = W[(size_t)(k0 + ty + i * 8) * N + n0 + tx];
    __syncthreads();
#pragma unroll
    for (int i = 0; i < 4; i++) {
        int n = ty + i * 8;
        float v = ts[tx][n];
        __half h, l; split16(v, h, l);
        size_t o = (size_t)(n0 + n) * K + k0 + tx;
        Bh[o] = h; Bl[o] = l;
    }
}

// -- fc1_xt weight reorder+transpose (single fp16); extra x-block: conv LUT --
__global__ void w16tx_kernel(const float* __restrict__ W,
                             const float* __restrict__ emb,
                             const float* __restrict__ cw,
                             __half* __restrict__ Bh)
{
    if (blockIdx.x == CONVL) {
        const int QTR = KW * NFLT * VOCAB / 4;   // 1664
        int base = blockIdx.y * QTR;
        for (int i = threadIdx.x; i < QTR; i += 256) {
            int idx = base + i;
            int f = idx % NFLT;
            int v = (idx / NFLT) % VOCAB;
            int k = idx / (NFLT * VOCAB);
            float acc = 0.f;
#pragma unroll 4
            for (int c = 0; c < EMBD; c++)
                acc = fmaf(emb[v * EMBD + c], cw[f * EMBD * KW + c * KW + k], acc);
            g_luth[(k * VOCAB + v) * LUTH + f] = __float2half_rn(acc);
        }
        return;
    }
    __shared__ float ts[32][33];
    int t = blockIdx.x;
    int n0 = blockIdx.y * 32;
    int tx = threadIdx.x & 31, ty = threadIdx.x >> 5;
#pragma unroll
    for (int i = 0; i < 4; i++) {
        int f = ty + i * 8;
        ts[f][tx] = W[(size_t)(f * CONVL + t) * OUTD + n0 + tx];
    }
    __syncthreads();
#pragma unroll
    for (int i = 0; i < 4; i++) {
        int n = ty + i * 8;
        Bh[(size_t)(n0 + n) * FLAT + t * 32 + tx] = __float2half_rn(ts[tx][n]);
    }
}

// =========================== fp16 MMA helpers ================================
#define ASTR 40
#define STG_H (128 * ASTR)       // stage stride in halfs (5120)
#define STG_B (STG_H * 2)        // stage stride in bytes (10240)

__device__ __forceinline__ uint32_t smem_u32(const void* p) {
    uint32_t a;
    asm("{ .reg .u64 t; cvta.to.shared.u64 t, %1; cvt.u32.u64 %0, t; }"
        : "=r"(a) : "l"(p));
    return a;
}
__device__ __forceinline__ void ldm4(uint32_t* r, uint32_t saddr) {
    asm volatile("ldmatrix.sync.aligned.m8n8.x4.shared.b16 {%0,%1,%2,%3}, [%4];"
        : "=r"(r[0]), "=r"(r[1]), "=r"(r[2]), "=r"(r[3]) : "r"(saddr));
}
__device__ __forceinline__ void mma16816(float* d, const uint32_t* a,
                                         uint32_t b0, uint32_t b1) {
    asm volatile(
        "mma.sync.aligned.m16n8k16.row.col.f32.f16.f16.f32 "
        "{%0,%1,%2,%3}, {%4,%5,%6,%7}, {%8,%9}, {%0,%1,%2,%3};"
        : "+f"(d[0]), "+f"(d[1]), "+f"(d[2]), "+f"(d[3])
        : "r"(a[0]), "r"(a[1]), "r"(a[2]), "r"(a[3]), "r"(b0), "r"(b1));
}

// ==== hgemm1: fc1 — A single fp16, B hi/lo, double-buffered, split-K ========
#define HG_A   0
#define HG_BH  (2 * STG_B)
#define HG_BL  (4 * STG_B)
#define HG_TOTAL (6 * STG_B)

__global__ void __launch_bounds__(256, 2) hgemm1(
    const __half* __restrict__ Ah,
    const __half* __restrict__ Bh, const __half* __restrict__ Bl,
    float* __restrict__ Cacc, int lda, int ldb, int ldc,
    int totalChunks, int chunksPerSplit)
{
    extern __shared__ char dsm[];
    __half* sAh = (__half*)(dsm + HG_A);
    __half* sBh = (__half*)(dsm + HG_BH);
    __half* sBl = (__half*)(dsm + HG_BL);

    int tid = threadIdx.x, lane = tid & 31, wid = tid >> 5;
    int mw = wid & 3, nw = wid >> 2;
    int m0 = blockIdx.y * 128, n0 = blockIdx.x * 128;

    int c0 = blockIdx.z * chunksPerSplit;
    int c1 = min(totalChunks, c0 + chunksPerSplit);
    if (c0 >= c1) return;

    int r = tid >> 1, q = (tid & 1) * 16;
    const __half* pAh = Ah + (size_t)(m0 + r) * lda + q;
    const __half* pBh = Bh + (size_t)(n0 + r) * ldb + q;
    const __half* pBl = Bl + (size_t)(n0 + r) * ldb + q;
    __half* sAh_w = sAh + r * ASTR + q;
    __half* sBh_w = sBh + r * ASTR + q;
    __half* sBl_w = sBl + r * ASTR + q;

    uint32_t bAh = smem_u32(sAh);
    uint32_t bBh = smem_u32(sBh), bBl = smem_u32(sBl);
    int lrow = lane & 15, lcol = (lane >> 4) * 8;
    uint32_t ofsA[2], ofsB[4];
#pragma unroll
    for (int mt = 0; mt < 2; mt++)
        ofsA[mt] = ((mw * 32 + mt * 16 + lrow) * ASTR + lcol) * 2;
#pragma unroll
    for (int ng = 0; ng < 4; ng++)
        ofsB[ng] = ((nw * 64 + ng * 16 + lrow) * ASTR + lcol) * 2;

    float acc[2][8][4] = {};
    int p = 0;

    for (int c = c0; c < c1; c++) {
        size_t k0 = (size_t)c * 32;
        int sofh = p * STG_H;
        uint32_t sofb = p * STG_B;
        float4 v0, v1;
        v0 = *(const float4*)(pAh + k0); v1 = *(const float4*)(pAh + k0 + 8);
        *(float4*)(sAh_w + sofh) = v0; *(float4*)(sAh_w + sofh + 8) = v1;
        v0 = *(const float4*)(pBh + k0); v1 = *(const float4*)(pBh + k0 + 8);
        *(float4*)(sBh_w + sofh) = v0; *(float4*)(sBh_w + sofh + 8) = v1;
        v0 = *(const float4*)(pBl + k0); v1 = *(const float4*)(pBl + k0 + 8);
        *(float4*)(sBl_w + sofh) = v0; *(float4*)(sBl_w + sofh + 8) = v1;
        __syncthreads();

#pragma unroll
        for (int ks = 0; ks < 2; ks++) {
            uint32_t ah[2][4];
            ldm4(ah[0], bAh + sofb + ofsA[0] + ks * 32);
            ldm4(ah[1], bAh + sofb + ofsA[1] + ks * 32);
#pragma unroll
            for (int ng = 0; ng < 4; ng++) {
                uint32_t bh[4], bl[4];
                ldm4(bh, bBh + sofb + ofsB[ng] + ks * 32);
                ldm4(bl, bBl + sofb + ofsB[ng] + ks * 32);
#pragma unroll
                for (int mt = 0; mt < 2; mt++) {
                    float* d0 = acc[mt][2 * ng];
                    float* d1 = acc[mt][2 * ng + 1];
                    mma16816(d0, ah[mt], bh[0], bh[2]);
                    mma16816(d0, ah[mt], bl[0], bl[2]);
                    mma16816(d1, ah[mt], bh[1], bh[3]);
                    mma16816(d1, ah[mt], bl[1], bl[3]);
                }
            }
        }
        p ^= 1;
    }

    int gid = lane >> 2, tig = lane & 3;
#pragma unroll
    for (int mt = 0; mt < 2; mt++) {
        int row = m0 + mw * 32 + mt * 16 + gid;
#pragma unroll
        for (int nt = 0; nt < 8; nt++) {
            int col = n0 + nw * 64 + nt * 8 + tig * 2;
            float* p0 = Cacc + (size_t)row * ldc + col;
            float* p1 = Cacc + (size_t)(row + 8) * ldc + col;
            atomicAdd(p0,     acc[mt][nt][0]);
            atomicAdd(p0 + 1, acc[mt][nt][1]);
            atomicAdd(p1,     acc[mt][nt][2]);
            atomicAdd(p1 + 1, acc[mt][nt][3]);
        }
    }
}

// == f2gemm: fc2 — A from fp32 h1acc (+bias,relu) split hi/lo in-kernel ======
__global__ void __launch_bounds__(256, 2) f2gemm(
    const float* __restrict__ Aacc, const float* __restrict__ abias,
    const __half* __restrict__ Bh, const __half* __restrict__ Bl,
    float* __restrict__ Cacc, int lda, int ldb, int ldc,
    int totalChunks, int chunksPerSplit)
{
    __shared__ __half sAh[128 * ASTR], sAl[128 * ASTR];
    __shared__ __half sBh[128 * ASTR], sBl[128 * ASTR];

    int tid = threadIdx.x, lane = tid & 31, wid = tid >> 5;
    int mw = wid & 3, nw = wid >> 2;
    int m0 = blockIdx.y * 128, n0 = blockIdx.x * 128;

    int c0 = blockIdx.z * chunksPerSplit;
    int c1 = min(totalChunks, c0 + chunksPerSplit);
    if (c0 >= c1) return;

    int r = tid >> 1, q = (tid & 1) * 16;
    const float* pA = Aacc + (size_t)(m0 + r) * lda + q;
    const __half* pBh = Bh + (size_t)(n0 + r) * ldb + q;
    const __half* pBl = Bl + (size_t)(n0 + r) * ldb + q;
    __half* sAh_w = sAh + r * ASTR + q;
    __half* sAl_w = sAl + r * ASTR + q;
    __half* sBh_w = sBh + r * ASTR + q;
    __half* sBl_w = sBl + r * ASTR + q;

    uint32_t bAh = smem_u32(sAh), bAl = smem_u32(sAl);
    uint32_t bBh = smem_u32(sBh), bBl = smem_u32(sBl);
    int lrow = lane & 15, lcol = (lane >> 4) * 8;
    uint32_t ofsA[2], ofsB[4];
#pragma unroll
    for (int mt = 0; mt < 2; mt++)
        ofsA[mt] = ((mw * 32 + mt * 16 + lrow) * ASTR + lcol) * 2;
#pragma unroll
    for (int ng = 0; ng < 4; ng++)
        ofsB[ng] = ((nw * 64 + ng * 16 + lrow) * ASTR + lcol) * 2;

    float acc[2][8][4] = {};

    for (int c = c0; c < c1; c++) {
        size_t k0 = (size_t)c * 32;
        float av[16];
#pragma unroll
        for (int i = 0; i < 4; i++)
            *(float4*)&av[i * 4] = *(const float4*)(pA + k0 + i * 4);
        __half2 hh[8], ll[8];
#pragma unroll
        for (int i = 0; i < 8; i++) {
            float u0 = fmaxf(av[i * 2]     + __ldg(abias + k0 + q + i * 2),     0.f);
            float u1 = fmaxf(av[i * 2 + 1] + __ldg(abias + k0 + q + i * 2 + 1), 0.f);
            __half h0, l0, h1, l1;
            split16(u0, h0, l0); split16(u1, h1, l1);
            hh[i] = __halves2half2(h0, h1);
            ll[i] = __halves2half2(l0, l1);
        }
        *(float4*)sAh_w = *(float4*)&hh[0];
        *(float4*)(sAh_w + 8) = *(float4*)&hh[4];
        *(float4*)sAl_w = *(float4*)&ll[0];
        *(float4*)(sAl_w + 8) = *(float4*)&ll[4];

        float4 v0, v1;
        v0 = *(const float4*)(pBh + k0); v1 = *(const float4*)(pBh + k0 + 8);
        *(float4*)sBh_w = v0; *(float4*)(sBh_w + 8) = v1;
        v0 = *(const float4*)(pBl + k0); v1 = *(const float4*)(pBl + k0 + 8);
        *(float4*)sBl_w = v0; *(float4*)(sBl_w + 8) = v1;
        __syncthreads();

#pragma unroll
        for (int ks = 0; ks < 2; ks++) {
            uint32_t ah[2][4], al[2][4];
            ldm4(ah[0], bAh + ofsA[0] + ks * 32);
            ldm4(ah[1], bAh + ofsA[1] + ks * 32);
            ldm4(al[0], bAl + ofsA[0] + ks * 32);
            ldm4(al[1], bAl + ofsA[1] + ks * 32);
#pragma unroll
            for (int ng = 0; ng < 4; ng++) {
                uint32_t bh[4], bl[4];
                ldm4(bh, bBh + ofsB[ng] + ks * 32);
                ldm4(bl, bBl + ofsB[ng] + ks * 32);
#pragma unroll
                for (int mt = 0; mt < 2; mt++) {
                    float* d0 = acc[mt][2 * ng];
                    float* d1 = acc[mt][2 * ng + 1];
                    mma16816(d0, ah[mt], bh[0], bh[2]);
                    mma16816(d0, ah[mt], bl[0], bl[2]);
                    mma16816(d0, al[mt], bh[0], bh[2]);
                    mma16816(d1, ah[mt], bh[1], bh[3]);
                    mma16816(d1, ah[mt], bl[1], bl[3]);
                    mma16816(d1, al[mt], bh[1], bh[3]);
                }
            }
        }
        __syncthreads();
    }

    int gid = lane >> 2, tig = lane & 3;
#pragma unroll
    for (int mt = 0; mt < 2; mt++) {
        int row = m0 + mw * 32 + mt * 16 + gid;
#pragma unroll
        for (int nt = 0; nt < 8; nt++) {
            int col = n0 + nw * 64 + nt * 8 + tig * 2;
            float* p0 = Cacc + (size_t)row * ldc + col;
            float* p1 = Cacc + (size_t)(row + 8) * ldc + col;
            atomicAdd(p0,     acc[mt][nt][0]);
            atomicAdd(p0 + 1, acc[mt][nt][1]);
            atomicAdd(p1,     acc[mt][nt][2]);
            atomicAdd(p1 + 1, acc[mt][nt][3]);
        }
    }
}

// == fused conv + fc1_xt GEMM: fp16 LUT/A, single-fp16 B, double-buffered ====
#define CG_LUT   0
#define CG_BIAS  (CG_LUT + KW * VOCAB * LUTH * 2)          // 16640
#define CG_TOK   (CG_BIAS + 128)                            // 16768
#define CG_AH    (CG_TOK + 128 * TOKSLAB * 4)               // 34688
#define CG_BH    (CG_AH + 2 * STG_B)                        // 55168
#define CG_TOTAL (CG_BH + 2 * STG_B)                        // 75648

__global__ void __launch_bounds__(256, 2) cgemm(
    const int* __restrict__ target, const float* __restrict__ convbias,
    const __half* __restrict__ Bh, float* __restrict__ Cacc)
{
    extern __shared__ char dsm[];
    __half* lut_s = (__half*)(dsm + CG_LUT);
    float* bias_s = (float*)(dsm + CG_BIAS);
    int*   tok_s  = (int*)(dsm + CG_TOK);
    __half* sAh = (__half*)(dsm + CG_AH);
    __half* sBh = (__half*)(dsm + CG_BH);

    int tid = threadIdx.x, lane = tid & 31, wid = tid >> 5;
    int mw = wid & 3, nw = wid >> 2;
    int m0 = blockIdx.y * 128;

    int c0 = blockIdx.z * CPS_XT;
    int c1 = min(CONVL, c0 + CPS_XT);
    if (c0 >= c1) return;

    for (int i = tid; i < KW * VOCAB * LUTH / 2; i += 256)
        ((uint32_t*)lut_s)[i] = ((const uint32_t*)g_luth)[i];
    if (tid < NFLT) bias_s[tid] = convbias[tid];
    for (int i = tid; i < 128 * TOKSLAB; i += 256) {
        int row = i / TOKSLAB, j = i - row * TOKSLAB;
        int tp = c0 + j;
        tok_s[i] = (tp < SEQ) ? target[(size_t)(m0 + row) * SEQ + tp] : 0;
    }

    int r = tid >> 1, q = (tid & 1) * 16;
    const __half* pBh = Bh + (size_t)r * FLAT + q;
    __half* sAh_w = sAh + r * ASTR + q;
    __half* sBh_w = sBh + r * ASTR + q;

    uint32_t bAh = smem_u32(sAh);
    uint32_t bBh = smem_u32(sBh);
    int lrow = lane & 15, lcol = (lane >> 4) * 8;
    uint32_t ofsA[2], ofsB[4];
#pragma unroll
    for (int mt = 0; mt < 2; mt++)
        ofsA[mt] = ((mw * 32 + mt * 16 + lrow) * ASTR + lcol) * 2;
#pragma unroll
    for (int ng = 0; ng < 4; ng++)
        ofsB[ng] = ((nw * 64 + ng * 16 + lrow) * ASTR + lcol) * 2;

    float acc[2][8][4] = {};
    __syncthreads();

    __half2 bias2[8];
#pragma unroll
    for (int i = 0; i < 8; i++)
        bias2[i] = __floats2half2_rn(bias_s[q + i * 2], bias_s[q + i * 2 + 1]);
    int tkreg[KW];
#pragma unroll
    for (int k = 0; k < KW; k++) tkreg[k] = tok_s[r * TOKSLAB + k];

    const __half2 z2 = __float2half2_rn(0.f);
    int p = 0;

    for (int c = c0; c < c1; c++) {
        int cc = c - c0;
        size_t k0 = (size_t)c * 32;
        float4 bh0 = *(const float4*)(pBh + k0);
        float4 bh1 = *(const float4*)(pBh + k0 + 8);

        __half2 a2[8];
#pragma unroll
        for (int i = 0; i < 8; i++) a2[i] = bias2[i];
#pragma unroll
        for (int k = 0; k < KW; k++) {
            const __half2* lp = (const __half2*)&lut_s[(k * VOCAB + tkreg[k]) * LUTH + q];
#pragma unroll
            for (int i = 0; i < 8; i++) a2[i] = __hadd2(a2[i], lp[i]);
        }
#pragma unroll
        for (int i = 0; i < 8; i++) a2[i] = __hmax2(a2[i], z2);

        int sofh = p * STG_H;
        uint32_t sofb = p * STG_B;
        *(float4*)(sAh_w + sofh) = *(float4*)&a2[0];
        *(float4*)(sAh_w + sofh + 8) = *(float4*)&a2[4];
        *(float4*)(sBh_w + sofh) = bh0; *(float4*)(sBh_w + sofh + 8) = bh1;

#pragma unroll
        for (int k = 0; k < KW - 1; k++) tkreg[k] = tkreg[k + 1];
        tkreg[KW - 1] = tok_s[r * TOKSLAB + cc + KW];
        __syncthreads();

#pragma unroll
        for (int ks = 0; ks < 2; ks++) {
            uint32_t ah[2][4];
            ldm4(ah[0], bAh + sofb + ofsA[0] + ks * 32);
            ldm4(ah[1], bAh + sofb + ofsA[1] + ks * 32);
#pragma unroll
            for (int ng = 0; ng < 4; ng++) {
                uint32_t bh[4];
                ldm4(bh, bBh + sofb + ofsB[ng] + ks * 32);
#pragma unroll
                for (int mt = 0; mt < 2; mt++) {
                    mma16816(acc[mt][2 * ng],     ah[mt], bh[0], bh[2]);
                    mma16816(acc[mt][2 * ng + 1], ah[mt], bh[1], bh[3]);
                }
            }
        }
        p ^= 1;
    }

    int gid = lane >> 2, tig = lane & 3;
#pragma unroll
    for (int mt = 0; mt < 2; mt++) {
        int row = m0 + mw * 32 + mt * 16 + gid;
#pragma unroll
        for (int nt = 0; nt < 8; nt++) {
            int col = nw * 64 + nt * 8 + tig * 2;
            float* p0 = Cacc + (size_t)row * OUTD + col;
            float* p1 = Cacc + (size_t)(row + 8) * OUTD + col;
            atomicAdd(p0,     acc[mt][nt][0]);
            atomicAdd(p0 + 1, acc[mt][nt][1]);
            atomicAdd(p1,     acc[mt][nt][2]);
            atomicAdd(p1 + 1, acc[mt][nt][3]);
        }
    }
}

// == dual-node CSR gather: nodes (i, i+1) with interleaved load chains ========
__device__ __forceinline__ void gather_row2(const float* __restrict__ yv,
                                            int i, int lane,
                                            float& ta, float& tb,
                                            int& dega, int& degb)
{
    int rr = (lane < 3) ? g_rowptr[i + lane] : 0;
    int r0a = __shfl_sync(0xffffffffu, rr, 0);
    int r1a = __shfl_sync(0xffffffffu, rr, 1);
    int r1b = __shfl_sync(0xffffffffu, rr, 2);
    int r0b = r1a;
    dega = r1a - r0a;
    degb = r1b - r0b;

    ta = yv[(size_t)i * DIM + lane];
    tb = yv[(size_t)(i + 1) * DIM + lane];

    int ea = (r0a + lane < r1a) ? g_esorted[r0a + lane] : 0;
    int eb = (r0b + lane < r1b) ? g_esorted[r0b + lane] : 0;
    int cnta = min(dega, 32);
    int cntb = min(degb, 32);

    float aa = 0.f, ab = 0.f;
    if (cnta > 0) {
        int s = __shfl_sync(0xffffffffu, ea, 0);
        aa = yv[(size_t)s * DIM + lane];
    }
    if (cntb > 0) {
        int s = __shfl_sync(0xffffffffu, eb, 0);
        ab = yv[(size_t)s * DIM + lane];
    }
    int mx = max(cnta, cntb);
    for (int j = 1; j < mx; j++) {
        if (j < cnta) {
            int s = __shfl_sync(0xffffffffu, ea, j);
            float n = yv[(size_t)s * DIM + lane];
            ta += aa; aa = n;
        }
        if (j < cntb) {
            int s = __shfl_sync(0xffffffffu, eb, j);
            float n = yv[(size_t)s * DIM + lane];
            tb += ab; ab = n;
        }
    }
    if (cnta > 0) ta += aa;
    if (cntb > 0) tb += ab;

    // rare tails (degree > 32)
    for (int base = r0a + 32; base < r1a; base += 32) {
        int s = (base + lane < r1a) ? g_esorted[base + lane] : 0;
        int c = min(r1a - base, 32);
        for (int j = 0; j < c; j++) {
            int sj = __shfl_sync(0xffffffffu, s, j);
            ta += yv[(size_t)sj * DIM + lane];
        }
    }
    for (int base = r0b + 32; base < r1b; base += 32) {
        int s = (base + lane < r1b) ? g_esorted[base + lane] : 0;
        int c = min(r1b - base, 32);
        for (int j = 0; j < c; j++) {
            int sj = __shfl_sync(0xffffffffu, s, j);
            tb += yv[(size_t)sj * DIM + lane];
        }
    }
}

// ---- smem-broadcast matmul: acc += vec(32, in tbuf slot) @ W[32][32] --------
__device__ __forceinline__ float bcast_matvec(const float* __restrict__ tslot,
                                              const float* __restrict__ Ws,
                                              int lane, float acc)
{
#pragma unroll
    for (int k = 0; k < 8; k++) {
        float4 v = *(const float4*)&tslot[k * 4];   // broadcast LDS.128
        acc = fmaf(v.x, Ws[(k * 4 + 0) * DIM + lane], acc);
        acc = fmaf(v.y, Ws[(k * 4 + 1) * DIM + lane], acc);
        acc = fmaf(v.z, Ws[(k * 4 + 2) * DIM + lane], acc);
        acc = fmaf(v.w, Ws[(k * 4 + 3) * DIM + lane], acc);
    }
    return acc;
}

// ---- layer 0 tail (dual-node): gather + relu(t+ba)@Wb+bb + BN stats --------
__global__ void __launch_bounds__(256) mlp2agg_kernel(
    const float* __restrict__ p, const float* __restrict__ wb,
    const float* __restrict__ ba, const float* __restrict__ bb,
    float* __restrict__ y, float* __restrict__ stats)
{
    __shared__ float wb_s[DIM * DIM];
    __shared__ float tbuf[512];
    int tid = threadIdx.x;
    for (int i = tid; i < DIM * DIM; i += blockDim.x) wb_s[i] = wb[i];
    __syncthreads();

    int lane = tid & 31;
    int wsl = (tid >> 5) * 64;
    float* slotA = &tbuf[wsl];
    float* slotB = &tbuf[wsl + 32];
    int warpId = blockIdx.x * (blockDim.x >> 5) + (tid >> 5);
    int nWarps = gridDim.x * (blockDim.x >> 5);
    float bav = ba[lane], bbv = bb[lane];
    float s0 = 0.f, s1 = 0.f;

    for (int i = warpId * 2; i < N_ATOMS; i += nWarps * 2) {
        float ta, tb; int dega, degb;
        gather_row2(p, i, lane, ta, tb, dega, degb);
        float ha = fmaxf(ta + bav, 0.f);
        float hb = fmaxf(tb + bav, 0.f);
        slotA[lane] = ha; slotB[lane] = hb;
        __syncwarp();
        float acca = bcast_matvec(slotA, wb_s, lane, bbv);
        float accb = bcast_matvec(slotB, wb_s, lane, bbv);
        __syncwarp();
        float yva = fmaxf(acca, 0.f);
        float yvb = fmaxf(accb, 0.f);
        y[(size_t)i * DIM + lane] = yva;
        y[(size_t)(i + 1) * DIM + lane] = yvb;
        s0 += yva + yvb;
        s1 += yva * yva + yvb * yvb;
    }
    atomicAdd(&stats[lane], s0);
    atomicAdd(&stats[DIM + lane], s1);
}

// == fused full GIN layer (dual-node): BN fold + gather + MLP + stats ========
__global__ void __launch_bounds__(256) ginfull_kernel(
    const float* __restrict__ y_in, const float* __restrict__ wa,
    const float* __restrict__ ba, const float* __restrict__ wb,
    const float* __restrict__ bb, const float* __restrict__ gamma,
    const float* __restrict__ beta, const float* __restrict__ statsIn,
    float* __restrict__ y_out, float* __restrict__ statsOut)
{
    __shared__ float wa_s[DIM * DIM], wb_s[DIM * DIM];
    __shared__ float sc_s[DIM], sh_s[DIM], shwa_s[DIM];
    __shared__ float tbuf[512];
    int tid = threadIdx.x;
    if (tid < DIM) {
        float mu = statsIn[tid] * (1.0f / N_ATOMS);
        float var = statsIn[DIM + tid] * (1.0f / N_ATOMS) - mu * mu;
        float sc = gamma[tid] * rsqrtf(var + 1e-5f);
        sc_s[tid] = sc;
        sh_s[tid] = beta[tid] - mu * sc;
    }
    __syncthreads();
    for (int i = tid; i < DIM * DIM; i += blockDim.x) {
        wa_s[i] = sc_s[i >> 5] * wa[i];
        wb_s[i] = wb[i];
    }
    if (tid < DIM) {
        float acc = 0.f;
#pragma unroll
        for (int c = 0; c < DIM; c++) acc = fmaf(sh_s[c], wa[c * DIM + tid], acc);
        shwa_s[tid] = acc;
    }
    __syncthreads();

    int lane = tid & 31;
    int wsl = (tid >> 5) * 64;
    float* slotA = &tbuf[wsl];
    float* slotB = &tbuf[wsl + 32];
    int warpId = blockIdx.x * (blockDim.x >> 5) + (tid >> 5);
    int nWarps = gridDim.x * (blockDim.x >> 5);
    float bav = ba[lane], bbv = bb[lane], shwav = shwa_s[lane];
    float s0 = 0.f, s1 = 0.f;

    for (int i = warpId * 2; i < N_ATOMS; i += nWarps * 2) {
        float ta, tb; int dega, degb;
        gather_row2(y_in, i, lane, ta, tb, dega, degb);

        slotA[lane] = ta; slotB[lane] = tb;
        __syncwarp();
        float h1a = bcast_matvec(slotA, wa_s, lane,
                                 fmaf((float)(dega + 1), shwav, bav));
        float h1b = bcast_matvec(slotB, wa_s, lane,
                                 fmaf((float)(degb + 1), shwav, bav));
        __syncwarp();
        slotA[lane] = fmaxf(h1a, 0.f);
        slotB[lane] = fmaxf(h1b, 0.f);
        __syncwarp();
        float acca = bcast_matvec(slotA, wb_s, lane, bbv);
        float accb = bcast_matvec(slotB, wb_s, lane, bbv);
        __syncwarp();

        float yva = fmaxf(acca, 0.f);
        float yvb = fmaxf(accb, 0.f);
        y_out[(size_t)i * DIM + lane] = yva;
        y_out[(size_t)(i + 1) * DIM + lane] = yvb;
        s0 += yva + yvb;
        s1 += yva * yva + yvb * yvb;
    }
    atomicAdd(&statsOut[lane], s0);
    atomicAdd(&statsOut[DIM + lane], s1);
}

// ---------- global add pool (segmented, batch sorted, BN inline) ------------
__global__ void pool2_kernel(const float* __restrict__ y, const int* __restrict__ batch,
                             const float* __restrict__ statsIn,
                             const float* __restrict__ gamma, const float* __restrict__ beta,
                             float* __restrict__ xg)
{
    int lane = threadIdx.x & 31;
    int warp = (blockIdx.x * blockDim.x + threadIdx.x) >> 5;
    int nb = warp * 32;
    if (nb >= N_ATOMS) return;
    float mu = statsIn[lane] * (1.0f / N_ATOMS);
    float var = statsIn[DIM + lane] * (1.0f / N_ATOMS) - mu * mu;
    float sc = gamma[lane] * rsqrtf(var + 1e-5f);
    float sh = beta[lane] - mu * sc;

    int bt = (nb + lane < N_ATOMS) ? batch[nb + lane] : -1;
    int cur = __shfl_sync(0xffffffffu, bt, 0);
    float sum = 0.f;
    int last = min(32, N_ATOMS - nb);
    for (int j = 0; j < last; j++) {
        int b = __shfl_sync(0xffffffffu, bt, j);
        float v = fmaf(y[(size_t)(nb + j) * DIM + lane], sc, sh);
        if (b != cur) {
            atomicAdd(&xg[cur * DIM + lane], sum);
            sum = 0.f; cur = b;
        }
        sum += v;
    }
    atomicAdd(&xg[cur * DIM + lane], sum);
}

// ----- build xc (single fp16): fc1_xd + xt epilogue + LM --------------------
__global__ void xcfill_kernel(const float* __restrict__ xg, const float* __restrict__ w,
                              const float* __restrict__ bias,
                              const float* __restrict__ xtacc, const float* __restrict__ xtb,
                              const float* __restrict__ drug, const float* __restrict__ prot)
{
    int idx = blockIdx.x * blockDim.x + threadIdx.x;
    if (idx >= BGR * COMB) return;
    int b = idx / COMB;
    int j = idx - b * COMB;
    float v;
    if (j < OUTD) {
        float acc = bias[j];
#pragma unroll
        for (int c = 0; c < DIM; c++) acc = fmaf(xg[b * DIM + c], w[c * OUTD + j], acc);
        v = fmaxf(acc, 0.f);
    } else if (j < 2 * OUTD) {
        int o = j - OUTD;
        v = fmaxf(xtacc[b * OUTD + o] + xtb[o], 0.f);
    } else {
        int jj = j - 2 * OUTD;
        v = (jj < LMDIM) ? drug[b * LMDIM + jj] : prot[b * LMDIM + (jj - LMDIM)];
    }
    g_XCh[idx] = __float2half_rn(v);
}

// ------------- final output layer (fc2 epilogue fused in) -------------------
__global__ void out_kernel(const float* __restrict__ h2acc, const float* __restrict__ b2,
                           const float* __restrict__ w, const float* __restrict__ b,
                           float* __restrict__ out)
{
    int tid = threadIdx.x;
    int lane = tid & 31;
    int row = blockIdx.x * (blockDim.x >> 5) + (tid >> 5);
    if (row >= BGR) return;
    float acc = 0.f;
#pragma unroll
    for (int k = 0; k < H2DIM / 32; k++) {
        float h2 = fmaxf(h2acc[row * H2DIM + k * 32 + lane] + b2[k * 32 + lane], 0.f);
        acc = fmaf(h2, w[k * 32 + lane], acc);
    }
#pragma unroll
    for (int off = 16; off; off >>= 1) acc += __shfl_xor_sync(0xffffffffu, acc, off);
    if (lane == 0) out[row] = acc + b[0];
}

// ================================ launcher ===================================
extern "C" void kernel_launch(void* const* d_in, const int* in_sizes, int n_in,
                              void* d_out, int out_size)
{
    (void)in_sizes; (void)n_in; (void)out_size;
    const float* x        = (const float*)d_in[0];
    const int*   ei       = (const int*)d_in[1];
    const int*   batch    = (const int*)d_in[2];
    const int*   target   = (const int*)d_in[3];
    const float* drug_lm  = (const float*)d_in[4];
    const float* prot_lm  = (const float*)d_in[5];
    const float* w1a      = (const float*)d_in[6];
    const float* b1a      = (const float*)d_in[7];
    const float* w1b      = (const float*)d_in[8];
    const float* b1b      = (const float*)d_in[9];
    const float* gw_a     = (const float*)d_in[10];
    const float* gb_a     = (const float*)d_in[11];
    const float* gw_b     = (const float*)d_in[12];
    const float* gb_b     = (const float*)d_in[13];
    const float* bn_gamma = (const float*)d_in[14];
    const float* bn_beta  = (const float*)d_in[15];
    const float* fc1_xd_w = (const float*)d_in[16];
    const float* fc1_xd_b = (const float*)d_in[17];
    const float* emb      = (const float*)d_in[18];
    const float* convxt_w = (const float*)d_in[19];
    const float* convxt_b = (const float*)d_in[20];
    const float* fc1_xt_w = (const float*)d_in[21];
    const float* fc1_xt_b = (const float*)d_in[22];
    const float* fc1_w    = (const float*)d_in[23];
    const float* fc1_b    = (const float*)d_in[24];
    const float* fc2_w    = (const float*)d_in[25];
    const float* fc2_b    = (const float*)d_in[26];
    const float* out_w    = (const float*)d_in[27];
    const float* out_b    = (const float*)d_in[28];
    float* out = (float*)d_out;

    const int* srcp = ei;
    const int* dstp = ei + EDGES;

    void* vp;
    cudaGetSymbolAddress(&vp, g_p);      float* p_p     = (float*)vp;
    cudaGetSymbolAddress(&vp, g_y);      float* p_y     = (float*)vp;
    cudaGetSymbolAddress(&vp, g_y2);     float* p_y2    = (float*)vp;
    cudaGetSymbolAddress(&vp, g_stats);  float* p_stats = (float*)vp;
    cudaGetSymbolAddress(&vp, g_xg);     float* p_xg    = (float*)vp;
    cudaGetSymbolAddress(&vp, g_BxtH);   __half* p_BxtH = (__half*)vp;
    cudaGetSymbolAddress(&vp, g_B1H);    __half* p_B1H  = (__half*)vp;
    cudaGetSymbolAddress(&vp, g_B1L);    __half* p_B1L  = (__half*)vp;
    cudaGetSymbolAddress(&vp, g_B2H);    __half* p_B2H  = (__half*)vp;
    cudaGetSymbolAddress(&vp, g_B2L);    __half* p_B2L  = (__half*)vp;
    cudaGetSymbolAddress(&vp, g_XCh);    __half* p_XCh  = (__half*)vp;
    cudaGetSymbolAddress(&vp, g_xtacc);  float* p_xtacc = (float*)vp;
    cudaGetSymbolAddress(&vp, g_h1acc);  float* p_h1acc = (float*)vp;
    cudaGetSymbolAddress(&vp, g_h2acc);  float* p_h2acc = (float*)vp;

    cudaFuncSetAttribute(cgemm, cudaFuncAttributeMaxDynamicSharedMemorySize, CG_TOTAL);
    cudaFuncSetAttribute(hgemm1, cudaFuncAttributeMaxDynamicSharedMemorySize, HG_TOTAL);

    cudaStream_t s2;
    cudaStreamCreateWithFlags(&s2, cudaStreamNonBlocking);
    cudaEvent_t eFork, eJoin;
    cudaEventCreateWithFlags(&eFork, cudaEventDisableTiming);
    cudaEventCreateWithFlags(&eJoin, cudaEventDisableTiming);

    // (1) combo: proj78 + zero + hist   [main]
    combo_kernel<<<NPROJ + NZERO, 256>>>(x, w1a, p_p, dstp);
    cudaEventRecord(eFork, 0);

    // (2)(3)(4) CSR scan/scatter, then mlp2agg (submission #4 -> ncu capture)
    scanlb_kernel<<<NB_SCAN, 256>>>();
    scatter_kernel<<<(EDGES + 255) / 256, 256>>>(srcp, dstp);
    mlp2agg_kernel<<<1024, 256>>>(p_p, w1b, b1a, b1b, p_y, p_stats);

    // ---- branch B (s2): protein conv GEMM + weight conversions ----
    cudaStreamWaitEvent(s2, eFork, 0);
    { dim3 g(CONVL + 1, OUTD / 32);
      w16tx_kernel<<<g, 256, 0, s2>>>(fc1_xt_w, emb, convxt_w, p_BxtH); }
    {
        dim3 grid(1, BGR / 128, SPLITS_XT);
        cgemm<<<grid, 256, CG_TOTAL, s2>>>(target, convxt_b, p_BxtH, p_xtacc);
    }
    { dim3 g(COMB / 32, H1DIM / 32, 2);
      w16t2_kernel<<<g, 256, 0, s2>>>(fc1_w, p_B1H, p_B1L, fc2_w, p_B2H, p_B2L); }
    cudaEventRecord(eJoin, s2);

    // ---- branch A (main): GIN layers 1-4 + pool ----
    float* yin = p_y; float* yout = p_y2;
    for (int l = 1; l < 5; l++) {
        ginfull_kernel<<<1024, 256>>>(yin,
            gw_a + (l - 1) * DIM * DIM, gb_a + (l - 1) * DIM,
            gw_b + (l - 1) * DIM * DIM, gb_b + (l - 1) * DIM,
            bn_gamma + (l - 1) * DIM, bn_beta + (l - 1) * DIM,
            p_stats + (l - 1) * 2 * DIM, yout, p_stats + l * 2 * DIM);
        float* tmp = yin; yin = yout; yout = tmp;
    }
    pool2_kernel<<<(N_ATOMS / 32 + 7) / 8, 256>>>(yin, batch,
        p_stats + 4 * 2 * DIM, bn_gamma + 4 * DIM, bn_beta + 4 * DIM, p_xg);

    // join B: xcfill needs branch B's xtacc + weights
    cudaStreamWaitEvent(0, eJoin, 0);
    xcfill_kernel<<<(BGR * COMB + 255) / 256, 256>>>(
        p_xg, fc1_xd_w, fc1_xd_b, p_xtacc, fc1_xt_b, drug_lm, prot_lm);

    // head MLP
    {
        dim3 grid(H1DIM / 128, BGR / 128, 4);
        hgemm1<<<grid, 256, HG_TOTAL>>>(p_XCh, p_B1H, p_B1L, p_h1acc,
                                        COMB, COMB, H1DIM, COMB / 32, 18);
    }
    {
        dim3 grid(H2DIM / 128, BGR / 128, 16);
        f2gemm<<<grid, 256>>>(p_h1acc, fc1_b, p_B2H, p_B2L, p_h2acc,
                              H1DIM, H1DIM, H2DIM, H1DIM / 32, 2);
    }
    out_kernel<<<BGR / 8, 256>>>(p_h2acc, fc2_b, out_w, out_b, out);

    cudaEventDestroy(eFork);
    cudaEventDestroy(eJoin);
    cudaStreamDestroy(s2);
}